// round 10
// baseline (speedup 1.0000x reference)
#include <cuda_runtime.h>
#include <cuda_fp16.h>
#include <cstdint>

#define N_NODES 50000
#define N_EDGES 800000
#define NB_SCAN 196          // ceil(50000/256)

// ---------------- device scratch (allocation-free rule: __device__ globals) ----
__device__ float  g_dinv[N_NODES];
__device__ __align__(16) __half g_h  [N_NODES * 64];
__device__ __align__(16) float  g_x1 [N_NODES * 64];
__device__ __align__(16) float  g_x2 [N_NODES * 64];
__device__ int g_deg [N_NODES];
__device__ int g_ptr [N_NODES + 1];
__device__ int g_fill[N_NODES];
__device__ int g_bsum[NB_SCAN];
__device__ int g_csr_src[N_EDGES];
__device__ int          g_bar_count;   // zero-init; returns to 0 each launch
__device__ volatile int g_bar_gen;     // monotonically increasing across launches

// ---------------- software grid barrier (all blocks co-resident) ----------------
__device__ __forceinline__ void gridbar() {
    __syncthreads();
    if (threadIdx.x == 0) {
        __threadfence();                       // release prior writes
        int gen = g_bar_gen;
        if (atomicAdd(&g_bar_count, 1) == (int)gridDim.x - 1) {
            g_bar_count = 0;
            __threadfence();
            g_bar_gen = gen + 1;               // release the others
        } else {
            while (g_bar_gen == gen) __nanosleep(64);
        }
        __threadfence();
    }
    __syncthreads();
}

// ---------------- GEMM phase: H[N, DOUT] = X[N, 64] @ W[64, DOUT] -> fp16 -------
template <int DOUT>
__device__ void gemm_phase(const float* __restrict__ X, const float* __restrict__ W,
                           __half* __restrict__ H, char* sm) {
    constexpr int DIN  = 64;
    constexpr int C4   = DOUT / 4;
    constexpr int ROWS = 256 / C4;
    constexpr int XS   = 17;
    float4* sW  = (float4*)sm;
    float4* sX4 = (float4*)(sm + sizeof(float4) * DIN * C4);
    int tid = threadIdx.x;

    for (int i = tid; i < DIN * C4; i += 256) sW[i] = ((const float4*)W)[i];
    __syncthreads();

    constexpr int NT = (N_NODES + ROWS - 1) / ROWS;
    for (int t = blockIdx.x; t < NT; t += gridDim.x) {
        int rowbase = t * ROWS;
        for (int i = tid; i < ROWS * (DIN / 4); i += 256) {
            int r = i / (DIN / 4);
            int q = i % (DIN / 4);
            int row = rowbase + r;
            sX4[r * XS + q] = (row < N_NODES)
                ? ((const float4*)X)[(size_t)row * (DIN / 4) + q]
                : make_float4(0.f, 0.f, 0.f, 0.f);
        }
        __syncthreads();
        int c4 = tid % C4;
        int r  = tid / C4;
        int row = rowbase + r;
        if (row < N_NODES) {
            const float* sx = (const float*)&sX4[r * XS];
            float4 acc = make_float4(0.f, 0.f, 0.f, 0.f);
#pragma unroll
            for (int k = 0; k < DIN; k++) {
                float  xv = sx[k];
                float4 wv = sW[k * C4 + c4];
                acc.x = fmaf(xv, wv.x, acc.x);
                acc.y = fmaf(xv, wv.y, acc.y);
                acc.z = fmaf(xv, wv.z, acc.z);
                acc.w = fmaf(xv, wv.w, acc.w);
            }
            __half2 p0 = __floats2half2_rn(acc.x, acc.y);
            __half2 p1 = __floats2half2_rn(acc.z, acc.w);
            uint2 u;
            u.x = *(unsigned*)&p0;
            u.y = *(unsigned*)&p1;
            ((uint2*)H)[(size_t)row * C4 + c4] = u;
        }
        __syncthreads();
    }
}

// ---------------- agg phase: out = act(di*(Σ dinv[s]·h[s] + di·h[node]) + b) ----
__device__ __forceinline__ void acc8(float4& acc, unsigned long long u, float w) {
    unsigned lo = (unsigned)u, hi = (unsigned)(u >> 32);
    float2 f01 = __half22float2(*(__half2*)&lo);
    float2 f23 = __half22float2(*(__half2*)&hi);
    acc.x += f01.x * w;
    acc.y += f01.y * w;
    acc.z += f23.x * w;
    acc.w += f23.y * w;
}

template <int DOUT, bool TANH>
__device__ void agg_phase(const __half* __restrict__ H, const float* __restrict__ b,
                          float* __restrict__ OUT) {
    constexpr int C = DOUT / 4;
    int P = gridDim.x * 256;
    int g = blockIdx.x * 256 + threadIdx.x;
    const unsigned long long* H8 = (const unsigned long long*)H;

    for (int t = g; t < N_NODES * C; t += P) {
        int node = t / C;
        int lane = t % C;
        int beg = g_ptr[node];
        int end = g_ptr[node + 1];

        float4 acc = make_float4(0.f, 0.f, 0.f, 0.f);
        int e = beg;
        for (; e + 3 < end; e += 4) {
            int s0 = g_csr_src[e],     s1 = g_csr_src[e + 1];
            int s2 = g_csr_src[e + 2], s3 = g_csr_src[e + 3];
            float w0 = g_dinv[s0], w1 = g_dinv[s1];
            float w2 = g_dinv[s2], w3 = g_dinv[s3];
            unsigned long long u0 = __ldcg(&H8[(size_t)s0 * C + lane]);
            unsigned long long u1 = __ldcg(&H8[(size_t)s1 * C + lane]);
            unsigned long long u2 = __ldcg(&H8[(size_t)s2 * C + lane]);
            unsigned long long u3 = __ldcg(&H8[(size_t)s3 * C + lane]);
            acc8(acc, u0, w0);
            acc8(acc, u1, w1);
            acc8(acc, u2, w2);
            acc8(acc, u3, w3);
        }
        for (; e < end; e++) {
            int s0 = g_csr_src[e];
            acc8(acc, __ldcg(&H8[(size_t)s0 * C + lane]), g_dinv[s0]);
        }

        float di = g_dinv[node];
        unsigned long long uh = __ldcg(&H8[(size_t)node * C + lane]);
        unsigned lo = (unsigned)uh, hi = (unsigned)(uh >> 32);
        float2 h01 = __half22float2(*(__half2*)&lo);
        float2 h23 = __half22float2(*(__half2*)&hi);
        float4 bb = ((const float4*)b)[lane];
        float4 v;
        v.x = di * (acc.x + di * h01.x) + bb.x;
        v.y = di * (acc.y + di * h01.y) + bb.y;
        v.z = di * (acc.z + di * h23.x) + bb.z;
        v.w = di * (acc.w + di * h23.y) + bb.w;
        if (TANH) {
            v.x = tanhf(v.x); v.y = tanhf(v.y); v.z = tanhf(v.z); v.w = tanhf(v.w);
        }
        ((float4*)OUT)[(size_t)node * C + lane] = v;
    }
}

// ---------------- the single persistent kernel ----------------------------------
__global__ void __launch_bounds__(256, 4)
k_mega(const float* __restrict__ x, const int* __restrict__ ei,
       const float* __restrict__ W1, const float* __restrict__ b1,
       const float* __restrict__ W2, const float* __restrict__ b2,
       const float* __restrict__ W3, const float* __restrict__ b3,
       float* __restrict__ out) {
    __shared__ __align__(16) char SM[20736];   // max(gemm64, gemm32, scan) usage
    int tid = threadIdx.x;
    int g   = blockIdx.x * 256 + tid;
    int P   = gridDim.x * 256;
    int* s  = (int*)SM;

    // ---- P0: zero degree ----
    for (int i = g; i < N_NODES; i += P) g_deg[i] = 0;
    gridbar();

    // ---- P1: degree histogram (fire-and-forget atomics) ----
    for (int e = g; e < N_EDGES; e += P) atomicAdd(&g_deg[ei[N_EDGES + e]], 1);
    gridbar();

    // ---- P2a: chunk sums (196 chunks of 256 nodes) ----
    for (int c = blockIdx.x; c < NB_SCAN; c += gridDim.x) {
        int i = c * 256 + tid;
        s[tid] = (i < N_NODES) ? __ldcg(&g_deg[i]) : 0;
        __syncthreads();
        for (int o = 128; o > 0; o >>= 1) {
            if (tid < o) s[tid] += s[tid + o];
            __syncthreads();
        }
        if (tid == 0) g_bsum[c] = s[0];
        __syncthreads();
    }
    gridbar();

    // ---- P2b: block 0 exclusive-scans the 196 chunk sums ----
    if (blockIdx.x == 0) {
        int v = (tid < NB_SCAN) ? __ldcg(&g_bsum[tid]) : 0;
        s[tid] = v;
        __syncthreads();
        for (int o = 1; o < 256; o <<= 1) {
            int u = (tid >= o) ? s[tid - o] : 0;
            __syncthreads();
            s[tid] += u;
            __syncthreads();
        }
        if (tid < NB_SCAN) g_bsum[tid] = s[tid] - v;
    }
    gridbar();

    // ---- P2c: per-chunk exclusive scan -> ptr/fill + dinv ----
    for (int c = blockIdx.x; c < NB_SCAN; c += gridDim.x) {
        int i = c * 256 + tid;
        int v = (i < N_NODES) ? __ldcg(&g_deg[i]) : 0;
        s[tid] = v;
        __syncthreads();
        for (int o = 1; o < 256; o <<= 1) {
            int u = (tid >= o) ? s[tid - o] : 0;
            __syncthreads();
            s[tid] += u;
            __syncthreads();
        }
        int excl = s[tid] - v + __ldcg(&g_bsum[c]);
        if (i < N_NODES) {
            g_ptr[i]  = excl;
            g_fill[i] = excl;
            g_dinv[i] = rsqrtf((float)v + 1.0f);   // +1 self-loop
        }
        if (i == N_NODES) g_ptr[N_NODES] = N_EDGES;
        __syncthreads();
    }
    gridbar();

    // ---- P3: counting-sort fill (src index only) ----
    for (int e = g; e < N_EDGES; e += P) {
        int sn = ei[e];
        int d  = ei[N_EDGES + e];
        int pos = atomicAdd(&g_fill[d], 1);
        g_csr_src[pos] = sn;
    }
    gridbar();

    // ---- layer 1 ----
    gemm_phase<64>(x, W1, g_h, SM);
    gridbar();
    agg_phase<64, true>(g_h, b1, g_x1);
    gridbar();

    // ---- layer 2 ----
    gemm_phase<64>(g_x1, W2, g_h, SM);
    gridbar();
    agg_phase<64, true>(g_h, b2, g_x2);
    gridbar();

    // ---- layer 3 ----
    gemm_phase<32>(g_x2, W3, g_h, SM);
    gridbar();
    agg_phase<32, false>(g_h, b3, out);
    // no trailing barrier: kernel completion is the sync; bar state back to {0, gen+11}
}

// ---------------- launch --------------------------------------------------------
extern "C" void kernel_launch(void* const* d_in, const int* in_sizes, int n_in,
                              void* d_out, int out_size) {
    const float* x  = (const float*)d_in[0];
    const int*   ei = (const int*)d_in[1];      // JAX x64 disabled: int64 -> int32
    const float* W1 = (const float*)d_in[2];
    const float* b1 = (const float*)d_in[3];
    const float* W2 = (const float*)d_in[4];
    const float* b2 = (const float*)d_in[5];
    const float* W3 = (const float*)d_in[6];
    const float* b3 = (const float*)d_in[7];
    float*       out = (float*)d_out;

    int dev = 0;
    cudaGetDevice(&dev);
    int nsm = 0;
    cudaDeviceGetAttribute(&nsm, cudaDevAttrMultiProcessorCount, dev);
    int occ = 0;
    cudaOccupancyMaxActiveBlocksPerMultiprocessor(&occ, k_mega, 256, 0);
    if (occ < 1) occ = 1;
    if (nsm < 1) nsm = 1;
    int grid = nsm * occ;   // guaranteed co-resident -> gridbar cannot deadlock

    k_mega<<<grid, 256>>>(x, ei, W1, b1, W2, b2, W3, b3, out);
}